// round 11
// baseline (speedup 1.0000x reference)
#include <cuda_runtime.h>
#include <cstdint>

typedef unsigned long long u64;
typedef unsigned int u32;

#define HWDIM 224
#define HWPIX (HWDIM*HWDIM)   // 50176
#define NB    16
#define NTOK  49
#define CH    64
#define NOUT  80               // q(0..7) k(8..15) v(16..79)

// smem layout (floats):
//   qkv[49][80] @ 0      (3920)   -> overlaid by os[49][66] after AV
//   xt [49][68] @ 3920   (3332)   -> overlaid by att[49][58] after proj
#define XT_OFF 3920
#define XT_S   68
#define AT_OFF 3920
#define AT_S   58
#define OS_S   66
#define SMEM_FLOATS 7252
#define SMEM_BYTES  (SMEM_FLOATS*4)   // 29008

__device__ __forceinline__ void mma_tf32(float* d, const u32* a, u32 b0, u32 b1){
    asm volatile(
        "mma.sync.aligned.m16n8k8.row.col.f32.tf32.tf32.f32 "
        "{%0,%1,%2,%3}, {%4,%5,%6,%7}, {%8,%9}, {%0,%1,%2,%3};"
        : "+f"(d[0]), "+f"(d[1]), "+f"(d[2]), "+f"(d[3])
        : "r"(a[0]), "r"(a[1]), "r"(a[2]), "r"(a[3]), "r"(b0), "r"(b1));
}
__device__ __forceinline__ float tf32r(float f){
    u32 r;
    asm("cvt.rna.tf32.f32 %0, %1;" : "=r"(r) : "f"(f));
    return __uint_as_float(r);
}
__device__ __forceinline__ u32 ldg_u32(const float* p){
    return __float_as_uint(__ldg(p));
}

__global__ void __launch_bounds__(64, 8)
fused_kernel(const float* __restrict__ x,
             const float* __restrict__ Wq, const float* __restrict__ bq,
             const float* __restrict__ Wk, const float* __restrict__ bk,
             const float* __restrict__ Wv, const float* __restrict__ bv,
             const float* __restrict__ gamma,
             float* __restrict__ out)
{
    extern __shared__ float sp[];
    const int tid = threadIdx.x;
    const int blk = blockIdx.x;        // 16 b * 32 wh * 32 ww
    const int b   = blk >> 10;
    const int rem = blk & 1023;
    const int wh  = rem >> 5;
    const int ww  = rem & 31;
    const int h0  = wh * 7;
    const int w0  = ww * 7;

    const float g = __ldg(gamma);

    const int lane = tid & 31;
    const int grp  = lane >> 2, tig = lane & 3;
    const int half = tid >> 5;         // warp id: m-tile half

    float* xt  = sp + XT_OFF;          // [49][68] fp32 x (t-major)
    float* att = sp + AT_OFF;          // [49][58] (overlays xt later)
    const u32* pu = reinterpret_cast<const u32*>(sp);   // qkv as u32

    // ==== stage x window: thread = channel c (64 lanes = 64 channels) ====
    {
        const float* xc = x + (size_t)b * CH * HWPIX + (size_t)tid * HWPIX
                        + (size_t)h0 * HWDIM + w0;
        #pragma unroll
        for (int ph = 0; ph < 7; ph++) {
            #pragma unroll
            for (int pw = 0; pw < 7; pw++)
                xt[(ph * 7 + pw) * XT_S + tid] = __ldg(&xc[ph * HWDIM + pw]);
        }
    }
    __syncthreads();   // B1: xt complete

    // ==== proj: qkv[t][o] = sum_c x[t][c] * W[o][c] + bias ====
    {
        float d[2][10][4];
        #pragma unroll
        for (int mt = 0; mt < 2; mt++)
            #pragma unroll
            for (int nt = 0; nt < 10; nt++)
                #pragma unroll
                for (int e = 0; e < 4; e++) d[mt][nt][e] = 0.0f;

        const u32* xtu = reinterpret_cast<const u32*>(xt);
        const int r0 = (half * 2) * 16 + grp;
        const int r0c = min(r0, 48),      r1c = min(r0 + 8, 48);
        const int r2c = min(r0 + 16, 48), r3c = min(r0 + 24, 48);

        #pragma unroll
        for (int k0 = 0; k0 < 64; k0 += 8) {
            u32 a0[4], a1[4];
            a0[0] = xtu[r0c * XT_S + k0 + tig];
            a0[1] = xtu[r1c * XT_S + k0 + tig];
            a0[2] = xtu[r0c * XT_S + k0 + tig + 4];
            a0[3] = xtu[r1c * XT_S + k0 + tig + 4];
            a1[0] = xtu[r2c * XT_S + k0 + tig];
            a1[1] = xtu[r3c * XT_S + k0 + tig];
            a1[2] = xtu[r2c * XT_S + k0 + tig + 4];
            a1[3] = xtu[r3c * XT_S + k0 + tig + 4];
            #pragma unroll
            for (int nt = 0; nt < 10; nt++) {
                const float* Wb;
                int oo;
                if (nt == 0)      { Wb = Wq; oo = grp; }
                else if (nt == 1) { Wb = Wk; oo = grp; }
                else              { Wb = Wv; oo = (nt - 2) * 8 + grp; }
                u32 b0 = ldg_u32(Wb + oo * 64 + k0 + tig);
                u32 b1 = ldg_u32(Wb + oo * 64 + k0 + tig + 4);
                mma_tf32(d[0][nt], a0, b0, b1);
                mma_tf32(d[1][nt], a1, b0, b1);
            }
        }

        // epilogue: qkv[t][80] = d + bias (predicated t<49)
        #pragma unroll
        for (int mt = 0; mt < 2; mt++) {
            int ra = (half * 2 + mt) * 16 + grp;
            int rb = ra + 8;
            #pragma unroll
            for (int nt = 0; nt < 10; nt++) {
                int n0 = nt * 8 + 2 * tig;
                float b0v, b1v;
                if (nt == 0)      { b0v = __ldg(&bq[2*tig]); b1v = __ldg(&bq[2*tig+1]); }
                else if (nt == 1) { b0v = __ldg(&bk[2*tig]); b1v = __ldg(&bk[2*tig+1]); }
                else              { b0v = __ldg(&bv[(nt-2)*8 + 2*tig]);
                                    b1v = __ldg(&bv[(nt-2)*8 + 2*tig + 1]); }
                if (ra < NTOK)
                    *reinterpret_cast<float2*>(sp + ra * NOUT + n0)
                        = make_float2(d[mt][nt][0] + b0v, d[mt][nt][1] + b1v);
                if (rb < NTOK)
                    *reinterpret_cast<float2*>(sp + rb * NOUT + n0)
                        = make_float2(d[mt][nt][2] + b0v, d[mt][nt][3] + b1v);
            }
        }
    }
    __syncthreads();   // B2: qkv complete; xt dead -> att overlays

    // ==== zero att pad cols m=49..55 (warp-local rows only) ====
    {
        int r = half * 32 + lane;
        if (r < NTOK) {
            #pragma unroll
            for (int j = 0; j < 7; j++) att[r * AT_S + 49 + j] = 0.0f;
        }
    }

    // ==== QK^T: att[n][m] = <q_n, k_m>  (rows warp-local) ====
    #pragma unroll
    for (int mt = 0; mt < 2; mt++) {
        int r0 = (half * 2 + mt) * 16 + grp;
        int r1 = r0 + 8;
        int r0c = min(r0, 48), r1c = min(r1, 48);
        u32 a[4];
        a[0] = pu[r0c * NOUT + tig];
        a[1] = pu[r1c * NOUT + tig];
        a[2] = pu[r0c * NOUT + tig + 4];
        a[3] = pu[r1c * NOUT + tig + 4];
        float dq[7][4];
        #pragma unroll
        for (int nt = 0; nt < 7; nt++)
            #pragma unroll
            for (int e = 0; e < 4; e++) dq[nt][e] = 0.0f;
        #pragma unroll
        for (int nt = 0; nt < 7; nt++) {
            int m = nt * 8 + grp;
            u32 b0 = 0, b1 = 0;
            if (m < NTOK) {
                b0 = pu[m * NOUT + 8 + tig];
                b1 = pu[m * NOUT + 8 + tig + 4];
            }
            mma_tf32(dq[nt], a, b0, b1);
        }
        #pragma unroll
        for (int nt = 0; nt < 7; nt++) {
            int c0 = nt * 8 + 2 * tig;
            if (r0 < NTOK) {
                if (c0 < NTOK)     att[r0 * AT_S + c0]     = dq[nt][0];
                if (c0 + 1 < NTOK) att[r0 * AT_S + c0 + 1] = dq[nt][1];
            }
            if (r1 < NTOK) {
                if (c0 < NTOK)     att[r1 * AT_S + c0]     = dq[nt][2];
                if (c0 + 1 < NTOK) att[r1 * AT_S + c0 + 1] = dq[nt][3];
            }
        }
    }
    __syncwarp();

    // ==== softmax over keys m (rows, warp-local), gamma folded ====
    {
        int row = half * 32 + lane;
        if (row < NTOK) {
            float* ar = att + row * AT_S;
            float mx = ar[0];
            #pragma unroll 7
            for (int m = 1; m < NTOK; m++) mx = fmaxf(mx, ar[m]);
            float s = 0.0f;
            #pragma unroll 7
            for (int m = 0; m < NTOK; m++) {
                float e = __expf(ar[m] - mx);
                ar[m] = e;
                s += e;
            }
            float rs = g / s;
            #pragma unroll 7
            for (int m = 0; m < NTOK; m++) ar[m] = tf32r(ar[m] * rs);
        }
    }
    __syncwarp();

    // ==== AV: out[n][c] = sum_m att[n][m] * v[m][c] ====
    float dv[2][8][4];
    #pragma unroll
    for (int mt = 0; mt < 2; mt++)
        #pragma unroll
        for (int nt = 0; nt < 8; nt++)
            #pragma unroll
            for (int e = 0; e < 4; e++) dv[mt][nt][e] = 0.0f;
    {
        const u32* au = reinterpret_cast<const u32*>(att);
        int r0 = (half * 2) * 16 + grp;
        int r0c = min(r0, 48),      r1c = min(r0 + 8, 48);
        int r2c = min(r0 + 16, 48), r3c = min(r0 + 24, 48);
        #pragma unroll
        for (int ks = 0; ks < 7; ks++) {
            int k0 = ks * 8;
            u32 a0[4], a1[4];
            a0[0] = au[r0c * AT_S + k0 + tig];
            a0[1] = au[r1c * AT_S + k0 + tig];
            a0[2] = au[r0c * AT_S + k0 + tig + 4];
            a0[3] = au[r1c * AT_S + k0 + tig + 4];
            a1[0] = au[r2c * AT_S + k0 + tig];
            a1[1] = au[r3c * AT_S + k0 + tig];
            a1[2] = au[r2c * AT_S + k0 + tig + 4];
            a1[3] = au[r3c * AT_S + k0 + tig + 4];
            #pragma unroll
            for (int nt = 0; nt < 8; nt++) {
                int c = nt * 8 + grp;
                u32 b0 = 0, b1 = 0;
                int m0 = k0 + tig;
                if (ks < 6) {
                    b0 = pu[m0 * NOUT + 16 + c];
                    b1 = pu[(m0 + 4) * NOUT + 16 + c];
                } else {
                    if (m0 < NTOK) b0 = pu[m0 * NOUT + 16 + c];  // only m=48
                }
                mma_tf32(dv[0][nt], a0, b0, b1);
                mma_tf32(dv[1][nt], a1, b0, b1);
            }
        }
    }
    __syncthreads();   // B3: all qkv reads done -> os overlays qkv

    // ==== epilogue: os[t][66] over dead qkv ====
    #pragma unroll
    for (int mt = 0; mt < 2; mt++) {
        int r0 = (half * 2 + mt) * 16 + grp;
        int r1 = r0 + 8;
        #pragma unroll
        for (int nt = 0; nt < 8; nt++) {
            int c0 = nt * 8 + 2 * tig;
            if (r0 < NTOK)
                *reinterpret_cast<float2*>(sp + r0 * OS_S + c0)
                    = make_float2(dv[mt][nt][0], dv[mt][nt][1]);
            if (r1 < NTOK)
                *reinterpret_cast<float2*>(sp + r1 * OS_S + c0)
                    = make_float2(dv[mt][nt][2], dv[mt][nt][3]);
        }
    }
    __syncthreads();   // B4: os complete

    // ==== residual + store: out = os + x (gamma already applied) ====
    for (int u = tid; u < 98; u += 64) {
        int p  = u >> 1;
        int ch = (u & 1) * 32;
        int ph = p / 7, pw = p - ph * 7;
        const float* osr = sp + p * OS_S + ch;
        size_t gi = (size_t)b * CH * HWPIX + (size_t)(h0 + ph) * HWDIM + (w0 + pw)
                  + (size_t)ch * HWPIX;
        #pragma unroll 8
        for (int c = 0; c < 32; c++) {
            out[gi] = osr[c] + __ldg(&x[gi]);
            gi += HWPIX;
        }
    }
}

extern "C" void kernel_launch(void* const* d_in, const int* in_sizes, int n_in,
                              void* d_out, int out_size)
{
    const float* x     = (const float*)d_in[0];
    const float* Wq    = (const float*)d_in[1];
    const float* bq    = (const float*)d_in[2];
    const float* Wk    = (const float*)d_in[3];
    const float* bk    = (const float*)d_in[4];
    const float* Wv    = (const float*)d_in[5];
    const float* bv    = (const float*)d_in[6];
    const float* gamma = (const float*)d_in[7];
    float* out = (float*)d_out;

    cudaFuncSetAttribute(fused_kernel, cudaFuncAttributeMaxDynamicSharedMemorySize, SMEM_BYTES);

    fused_kernel<<<NB * 1024, 64, SMEM_BYTES>>>(x, Wq, bq, Wk, bk, Wv, bv, gamma, out);
}

// round 12
// speedup vs baseline: 1.3061x; 1.3061x over previous
#include <cuda_runtime.h>
#include <cstdint>

typedef unsigned long long u64;
typedef unsigned int u32;

#define HWDIM 224
#define HWPIX (HWDIM*HWDIM)   // 50176
#define NB    16
#define NTOK  49
#define CH    64
#define NOUT  80               // q(0..7) k(8..15) v(16..79)

// scratch: pixel-linear qkv [b][hw][80]
__device__ float g_qkv[(size_t)NB * HWPIX * NOUT];

__device__ __forceinline__ float tf32r(float f){
    u32 r;
    asm("cvt.rna.tf32.f32 %0, %1;" : "=r"(r) : "f"(f));
    return __uint_as_float(r);
}
__device__ __forceinline__ void mma_tf32(float* d, const u32* a, u32 b0, u32 b1){
    asm volatile(
        "mma.sync.aligned.m16n8k8.row.col.f32.tf32.tf32.f32 "
        "{%0,%1,%2,%3}, {%4,%5,%6,%7}, {%8,%9}, {%0,%1,%2,%3};"
        : "+f"(d[0]), "+f"(d[1]), "+f"(d[2]), "+f"(d[3])
        : "r"(a[0]), "r"(a[1]), "r"(a[2]), "r"(a[3]), "r"(b0), "r"(b1));
}

// ===================== K1: fused QKV projection (tf32 tensor cores) ===========
// 128 threads, 128 pixels/block. Warp = 32 px x 80 outs.
// smem floats: wct[64][84]@0 (5376) | xt[128][67]@5376 (8576) | bias@13952 (80)
// epilogue: os[128][84] overlays [0..10752)
#define WCT_S 84
#define XT_S  67
#define OFF_XT   5376
#define OFF_BIAS 13952
#define OS1_S    84
#define K1_SMEM_FLOATS 14032
#define K1_SMEM_BYTES  (K1_SMEM_FLOATS*4)   // 56128

__global__ void __launch_bounds__(128, 4)
proj_kernel(const float* __restrict__ x,
            const float* __restrict__ Wq, const float* __restrict__ bq,
            const float* __restrict__ Wk, const float* __restrict__ bk,
            const float* __restrict__ Wv, const float* __restrict__ bv)
{
    extern __shared__ float s1[];
    const int tid = threadIdx.x;
    const int blk = blockIdx.x;               // 16 * 392
    const int b   = blk / 392;
    const int hw0 = (blk - b * 392) * 128;

    // weights -> wct[c][84]: q(0..7) k(8..15) v(16..79), tf32-rounded
    for (int idx = tid; idx < 512; idx += 128) {
        int o = idx >> 6, c = idx & 63;
        s1[c * WCT_S + o]     = tf32r(__ldg(&Wq[idx]));
        s1[c * WCT_S + 8 + o] = tf32r(__ldg(&Wk[idx]));
    }
    for (int idx = tid; idx < 4096; idx += 128) {
        int o = idx >> 6, c = idx & 63;
        s1[c * WCT_S + 16 + o] = tf32r(__ldg(&Wv[idx]));
    }
    if (tid < 80)
        s1[OFF_BIAS + tid] = (tid < 8)  ? __ldg(&bq[tid])
                           : (tid < 16) ? __ldg(&bk[tid - 8])
                                        : __ldg(&bv[tid - 16]);

    // x -> xt[p][67]: thread = pixel; per-c LDG lane-consecutive (coalesced),
    // STS at odd stride 67 -> conflict-free.
    {
        const float* xb = x + (size_t)b * CH * HWPIX + hw0 + tid;
        float* xr = s1 + OFF_XT + tid * XT_S;
        #pragma unroll 8
        for (int c = 0; c < CH; c++)
            xr[c] = tf32r(__ldg(xb + (size_t)c * HWPIX));
    }
    __syncthreads();

    // compute: warp covers px [wid*32, wid*32+32)
    const int wid  = tid >> 5, lane = tid & 31;
    const int grp  = lane >> 2;        // 0..7
    const int tig  = lane & 3;         // 0..3
    const int pb   = wid * 32;

    float d[2][10][4];
    #pragma unroll
    for (int mt = 0; mt < 2; mt++)
        #pragma unroll
        for (int nt = 0; nt < 10; nt++)
            #pragma unroll
            for (int e = 0; e < 4; e++) d[mt][nt][e] = 0.0f;

    const u32* xtu = reinterpret_cast<const u32*>(s1 + OFF_XT);
    const u32* wcu = reinterpret_cast<const u32*>(s1);

    #pragma unroll
    for (int k0 = 0; k0 < 64; k0 += 8) {
        u32 a[2][4];
        #pragma unroll
        for (int mt = 0; mt < 2; mt++) {
            int base = pb + mt * 16;
            a[mt][0] = xtu[(base + grp)     * XT_S + k0 + tig];
            a[mt][1] = xtu[(base + grp + 8) * XT_S + k0 + tig];
            a[mt][2] = xtu[(base + grp)     * XT_S + k0 + tig + 4];
            a[mt][3] = xtu[(base + grp + 8) * XT_S + k0 + tig + 4];
        }
        #pragma unroll
        for (int nt = 0; nt < 10; nt++) {
            u32 b0 = wcu[(k0 + tig)     * WCT_S + nt * 8 + grp];
            u32 b1 = wcu[(k0 + tig + 4) * WCT_S + nt * 8 + grp];
            mma_tf32(d[0][nt], a[0], b0, b1);
            mma_tf32(d[1][nt], a[1], b0, b1);
        }
    }
    __syncthreads();   // xt/wct reads done; os overlays them

    // epilogue: os[p][84] = d + bias
    const float* sb = s1 + OFF_BIAS;
    #pragma unroll
    for (int mt = 0; mt < 2; mt++) {
        int p0 = pb + mt * 16 + grp;
        #pragma unroll
        for (int nt = 0; nt < 10; nt++) {
            int n0 = nt * 8 + 2 * tig;
            float b0v = sb[n0], b1v = sb[n0 + 1];
            *reinterpret_cast<float2*>(s1 + p0 * OS1_S + n0)
                = make_float2(d[mt][nt][0] + b0v, d[mt][nt][1] + b1v);
            *reinterpret_cast<float2*>(s1 + (p0 + 8) * OS1_S + n0)
                = make_float2(d[mt][nt][2] + b0v, d[mt][nt][3] + b1v);
        }
    }
    __syncthreads();

    // coalesced stream to g_qkv (skip the 4-float pad per row)
    float4* dst = reinterpret_cast<float4*>(g_qkv + ((size_t)b * HWPIX + hw0) * NOUT);
    for (int i = tid; i < 2560; i += 128) {
        int p  = i / 20;
        int c4 = i - p * 20;
        dst[i] = *reinterpret_cast<const float4*>(s1 + p * OS1_S + c4 * 4);
    }
}

// ===================== K2: windowed attention (tf32, 1 window / 64 thr) =======
// 64 threads = 2 warps, 1 window; 8 blocks/SM.
// smem (6964 floats): qkv[49][84]@0 (4116) | att[49][58]@4116 (2848)
// os[49][66] overlays qkv region after AV.
#define QKV_S 84
#define AT_S 58
#define ATT_OFF 4116
#define OS_STRIDE 66
#define K2_SMEM_FLOATS 6964
#define K2_SMEM_BYTES  (K2_SMEM_FLOATS*4)   // 27856

__global__ void __launch_bounds__(64, 8)
attn_kernel(const float* __restrict__ x,
            const float* __restrict__ gamma,
            float* __restrict__ out)
{
    extern __shared__ float sp[];
    const int tid = threadIdx.x;
    const int blk = blockIdx.x;        // 16 b * 32 wh * 32 ww
    const int b   = blk >> 10;
    const int rem = blk & 1023;
    const int wh  = rem >> 5;
    const int ww  = rem & 31;
    const int h0  = wh * 7;
    const int w0  = ww * 7;

    const float g = __ldg(gamma);

    const int wid  = tid >> 5, lane = tid & 31;
    const int grp  = lane >> 2, tig = lane & 3;
    const int half = wid;              // m-tile half {0,1}

    float* att = sp + ATT_OFF;         // [49][58]
    const u32* pu = reinterpret_cast<const u32*>(sp);

    // ---- stage qkv: 49 px * 20 float4 -> rows stride 84 ----
    const float* gq = g_qkv + ((size_t)b * HWPIX + (size_t)h0 * HWDIM + w0) * NOUT;
    for (int i = tid; i < 980; i += 64) {
        int ph = i / 140;
        int rr = i - ph * 140;
        int pw = rr / 20;
        int c4 = rr - pw * 20;
        int t  = ph * 7 + pw;
        float4 v = __ldg(reinterpret_cast<const float4*>(gq + ((size_t)ph * HWDIM + pw) * NOUT) + c4);
        *reinterpret_cast<float4*>(sp + t * QKV_S + c4 * 4) = v;
    }
    // zero att pad cols m = 49..55
    for (int i = tid; i < 343; i += 64) {
        int n = i / 7, j = i - n * 7;
        att[n * AT_S + 49 + j] = 0.0f;
    }
    __syncthreads();   // B1

    // ---- QK^T: att[n][m] = <q_n, k_m>  (rows warp-local) ----
    #pragma unroll
    for (int mt = 0; mt < 2; mt++) {
        int r0 = (half * 2 + mt) * 16 + grp;
        int r1 = r0 + 8;
        int r0c = min(r0, 48), r1c = min(r1, 48);
        u32 a[4];
        a[0] = pu[r0c * QKV_S + tig];
        a[1] = pu[r1c * QKV_S + tig];
        a[2] = pu[r0c * QKV_S + tig + 4];
        a[3] = pu[r1c * QKV_S + tig + 4];
        float dq[7][4];
        #pragma unroll
        for (int nt = 0; nt < 7; nt++)
            #pragma unroll
            for (int e = 0; e < 4; e++) dq[nt][e] = 0.0f;
        #pragma unroll
        for (int nt = 0; nt < 7; nt++) {
            int m = nt * 8 + grp;
            u32 b0 = 0, b1 = 0;
            if (m < NTOK) {
                b0 = pu[m * QKV_S + 8 + tig];
                b1 = pu[m * QKV_S + 8 + tig + 4];
            }
            mma_tf32(dq[nt], a, b0, b1);
        }
        #pragma unroll
        for (int nt = 0; nt < 7; nt++) {
            int c0 = nt * 8 + 2 * tig;
            if (r0 < NTOK) {
                if (c0 < NTOK)     att[r0 * AT_S + c0]     = dq[nt][0];
                if (c0 + 1 < NTOK) att[r0 * AT_S + c0 + 1] = dq[nt][1];
            }
            if (r1 < NTOK) {
                if (c0 < NTOK)     att[r1 * AT_S + c0]     = dq[nt][2];
                if (c0 + 1 < NTOK) att[r1 * AT_S + c0 + 1] = dq[nt][3];
            }
        }
    }
    __syncwarp();

    // ---- softmax over keys m (rows, warp-local), gamma folded ----
    {
        int row = half * 32 + lane;
        if (row < NTOK) {
            float* ar = att + row * AT_S;
            float mx = ar[0];
            #pragma unroll 7
            for (int m = 1; m < NTOK; m++) mx = fmaxf(mx, ar[m]);
            float s = 0.0f;
            #pragma unroll 7
            for (int m = 0; m < NTOK; m++) {
                float e = __expf(ar[m] - mx);
                ar[m] = e;
                s += e;
            }
            float rs = g / s;
            #pragma unroll 7
            for (int m = 0; m < NTOK; m++) ar[m] = tf32r(ar[m] * rs);
        }
    }
    __syncwarp();

    // ---- AV: out[n][c] = sum_m att[n][m] * v[m][c] ----
    float dv[2][8][4];
    #pragma unroll
    for (int mt = 0; mt < 2; mt++)
        #pragma unroll
        for (int nt = 0; nt < 8; nt++)
            #pragma unroll
            for (int e = 0; e < 4; e++) dv[mt][nt][e] = 0.0f;
    {
        const u32* au = reinterpret_cast<const u32*>(att);
        int r0 = (half * 2) * 16 + grp;
        int r0c = min(r0, 48),      r1c = min(r0 + 8, 48);
        int r2c = min(r0 + 16, 48), r3c = min(r0 + 24, 48);
        #pragma unroll
        for (int ks = 0; ks < 7; ks++) {
            int k0 = ks * 8;
            u32 a0[4], a1[4];
            a0[0] = au[r0c * AT_S + k0 + tig];
            a0[1] = au[r1c * AT_S + k0 + tig];
            a0[2] = au[r0c * AT_S + k0 + tig + 4];
            a0[3] = au[r1c * AT_S + k0 + tig + 4];
            a1[0] = au[r2c * AT_S + k0 + tig];
            a1[1] = au[r3c * AT_S + k0 + tig];
            a1[2] = au[r2c * AT_S + k0 + tig + 4];
            a1[3] = au[r3c * AT_S + k0 + tig + 4];
            #pragma unroll
            for (int nt = 0; nt < 8; nt++) {
                int c = nt * 8 + grp;
                u32 b0 = 0, b1 = 0;
                int m0 = k0 + tig;
                if (ks < 6) {
                    b0 = pu[m0 * QKV_S + 16 + c];
                    b1 = pu[(m0 + 4) * QKV_S + 16 + c];
                } else {
                    if (m0 < NTOK) b0 = pu[m0 * QKV_S + 16 + c];  // only m=48
                }
                mma_tf32(dv[0][nt], a0, b0, b1);
                mma_tf32(dv[1][nt], a1, b0, b1);
            }
        }
    }
    __syncthreads();   // B2: qkv reads done -> os overlays

    // ---- epilogue: os[t][66] over dead qkv ----
    #pragma unroll
    for (int mt = 0; mt < 2; mt++) {
        int r0 = (half * 2 + mt) * 16 + grp;
        int r1 = r0 + 8;
        #pragma unroll
        for (int nt = 0; nt < 8; nt++) {
            int c0 = nt * 8 + 2 * tig;
            if (r0 < NTOK)
                *reinterpret_cast<float2*>(sp + r0 * OS_STRIDE + c0)
                    = make_float2(dv[mt][nt][0], dv[mt][nt][1]);
            if (r1 < NTOK)
                *reinterpret_cast<float2*>(sp + r1 * OS_STRIDE + c0)
                    = make_float2(dv[mt][nt][2], dv[mt][nt][3]);
        }
    }
    __syncthreads();   // B3

    // ---- residual + store ----
    for (int u = tid; u < 98; u += 64) {
        int p  = u >> 1;
        int ch = (u & 1) * 32;
        int ph = p / 7, pw = p - ph * 7;
        const float* osr = sp + p * OS_STRIDE + ch;
        size_t gi = (size_t)b * CH * HWPIX + (size_t)(h0 + ph) * HWDIM + (w0 + pw)
                  + (size_t)ch * HWPIX;
        #pragma unroll 8
        for (int c = 0; c < 32; c++) {
            out[gi] = osr[c] + __ldg(&x[gi]);
            gi += HWPIX;
        }
    }
}

extern "C" void kernel_launch(void* const* d_in, const int* in_sizes, int n_in,
                              void* d_out, int out_size)
{
    const float* x     = (const float*)d_in[0];
    const float* Wq    = (const float*)d_in[1];
    const float* bq    = (const float*)d_in[2];
    const float* Wk    = (const float*)d_in[3];
    const float* bk    = (const float*)d_in[4];
    const float* Wv    = (const float*)d_in[5];
    const float* bv    = (const float*)d_in[6];
    const float* gamma = (const float*)d_in[7];
    float* out = (float*)d_out;

    cudaFuncSetAttribute(proj_kernel, cudaFuncAttributeMaxDynamicSharedMemorySize, K1_SMEM_BYTES);
    cudaFuncSetAttribute(attn_kernel, cudaFuncAttributeMaxDynamicSharedMemorySize, K2_SMEM_BYTES);

    proj_kernel<<<NB * (HWPIX / 128), 128, K1_SMEM_BYTES>>>(x, Wq, bq, Wk, bk, Wv, bv);
    attn_kernel<<<NB * 1024, 64, K2_SMEM_BYTES>>>(x, gamma, out);
}